// round 14
// baseline (speedup 1.0000x reference)
#include <cuda_runtime.h>
#include <cuda_fp16.h>
#include <cstdint>

// LSTM_discriminator: B=2048, T=512, H=128, input dim 1.
// inputs: 0:x[2048,512] 1:hx0[2048,128] 2:cx0[2048,128] 3:W_ih[512,1]
//         4:W_hh[512,128] 5:b_ih[512] 6:b_hh[512] 7:W_mlp[1,128] 8:b_mlp[1]
// output: sigmoid(h_T @ W_mlp^T + b_mlp) -> [2048,1] fp32
//
// INT8 tensor path: gates^T[16,512] = h_s8[16,128] @ W_s8''^T per step via
// mma.sync.m16n8k32.s8 (K=32/instr, half the mma count of f16 K=16), exact s32
// accumulation, gate-major column permutation (col = w*32 + g*8 + jl) so each
// thread's 4 acc sets are a full LSTM cell. W pre-laid-out in fragment order.

#define Bsz 2048
#define Tsz 512
#define Hsz 128
#define ROWS_PER_CTA 16
#define NCTA (Bsz / ROWS_PER_CTA)    // 128
#define NTHREADS 512
#define HB 144                       // h row stride bytes (128 data + 16 pad; conflict-free)

#define OFF_H   0                    // s8 h [2][16][HB] = 4608
#define OFF_X   4608                 // float [2][16]
#define OFF_SF  4736                 // float [16][128] head scratch
#define DSMEM   (OFF_SF + 16 * 128 * 4)   // 12928

// W quantization: W ~ U(-s_ih, s_ih), s_ih = 1/sqrt(128)
#define WQSCALE 1436.8405f           // 127 / s_ih
#define SWSH    5.4806448e-6f        // s_ih / (127*127)
#define MAGICF  12582912.0f          // 1.5 * 2^23

__device__ uint32_t g_Bfrag[16 * 4 * 4 * 64];  // [w][g][kt][lane][2] s8x4-packed W fragments
__device__ float2   g_ub[512];                 // per permuted col: {scaled W_ih, scaled bias}

// ---------------------------------------------------------------------------
__device__ __forceinline__ uint32_t smem_u32(const void* p) {
    uint32_t a;
    asm("{ .reg .u64 t; cvta.to.shared.u64 t, %1; cvt.u32.u64 %0, t; }" : "=r"(a) : "l"(p));
    return a;
}
__device__ __forceinline__ void mma_s8(int* d, const uint32_t* a, uint32_t b0, uint32_t b1) {
    asm volatile(
        "mma.sync.aligned.m16n8k32.row.col.s32.s8.s8.s32 "
        "{%0,%1,%2,%3}, {%4,%5,%6,%7}, {%8,%9}, {%0,%1,%2,%3};"
        : "+r"(d[0]), "+r"(d[1]), "+r"(d[2]), "+r"(d[3])
        : "r"(a[0]), "r"(a[1]), "r"(a[2]), "r"(a[3]), "r"(b0), "r"(b1));
}
__device__ __forceinline__ uint32_t pack_h2(float lo, float hi) {
    uint32_t r; asm("cvt.rn.f16x2.f32 %0, %1, %2;" : "=r"(r) : "f"(hi), "f"(lo)); return r;
}
__device__ __forceinline__ __half2 tanh_h2(uint32_t x) {
    uint32_t r; asm("tanh.approx.f16x2 %0, %1;" : "=r"(r) : "r"(x));
    return *reinterpret_cast<__half2*>(&r);
}
__device__ __forceinline__ float tanha(float x) {
    float r; asm("tanh.approx.f32 %0, %1;" : "=f"(r) : "f"(x)); return r;
}
__device__ __forceinline__ float fsig(float x)  { return fmaf(0.5f, tanha(0.5f * x), 0.5f); }
__device__ __forceinline__ uint32_t pack_s8(int hi, int lo) {
    uint32_t r;
    asm("cvt.pack.sat.s8.s32.b32 %0, %1, %2, %3;" : "=r"(r) : "r"(hi), "r"(lo), "r"(0));
    return r;   // byte0 = sat8(lo), byte1 = sat8(hi)
}
__device__ __forceinline__ float acc2f(int acc) {   // exact for |acc| < 2^22
    return __int_as_float(0x4B400000 + acc) - MAGICF;
}

// ---------------------------------------------------------------------------
// prep: quantize permuted W into B-fragment layout; pack u/b (sigma-half fold
// on i,f,o kept in the f32 side: u,b scaled; W scale handled in epilogue).
// col = w*32 + g*8 + n  ->  gate row g*128 + w*8 + n.
// Fragment [w][g][kt][lane][e]: n = lane>>2, k = kt*32 + (lane&3)*4 + e*16 + i.
// ---------------------------------------------------------------------------
__global__ void lstm_prep_kernel(const float* __restrict__ Whh,
                                 const float* __restrict__ Wih,
                                 const float* __restrict__ bih,
                                 const float* __restrict__ bhh) {
    int idx = blockIdx.x * blockDim.x + threadIdx.x;   // one uint32 each
    if (idx >= 16 * 4 * 4 * 64) return;
    int e  = idx & 1;
    int l  = (idx >> 1) & 31;
    int kt = (idx >> 6) & 3;
    int g  = (idx >> 8) & 3;
    int w  = (idx >> 10) & 15;
    int n  = l >> 2;
    int kb = kt * 32 + (l & 3) * 4 + e * 16;
    int grow = g * 128 + w * 8 + n;
    uint32_t packed = 0;
#pragma unroll
    for (int i = 0; i < 4; i++) {
        int q = __float2int_rn(Whh[grow * Hsz + kb + i] * WQSCALE);
        packed |= (uint32_t)(q & 0xFF) << (8 * i);
    }
    g_Bfrag[idx] = packed;

    if (idx < 512) {
        int cw = idx >> 5, cg = (idx >> 3) & 3, cj = idx & 7;
        int gr2 = cg * 128 + cw * 8 + cj;
        float sc2 = (cg == 2) ? 1.0f : 0.5f;
        g_ub[idx] = make_float2(sc2 * Wih[gr2], sc2 * (bih[gr2] + bhh[gr2]));
    }
}

// ---------------------------------------------------------------------------
// main persistent kernel: 128 CTAs x 512 threads (16 warps).
// Warp w: W fragments (int8) for cols [w*32, w*32+32) register-resident.
// Thread: rows {r, r+8}, hidden pair j0 = w*8 + (lane&3)*2.
// ---------------------------------------------------------------------------
__global__ __launch_bounds__(NTHREADS, 1)
void lstm_main_kernel(const float* __restrict__ x,
                      const float* __restrict__ hx0,
                      const float* __restrict__ cx0,
                      const float* __restrict__ Wm,
                      const float* __restrict__ bm,
                      float* __restrict__ out) {
    extern __shared__ __align__(16) char dyn[];
    const uint32_t smem_base = smem_u32(dyn);

    const int tid  = threadIdx.x;
    const int w    = tid >> 5;
    const int lane = tid & 31;
    const int rowbase = blockIdx.x * ROWS_PER_CTA;

    float* shX = reinterpret_cast<float*>(dyn + OFF_X);   // [2][16]

    // ---- load W fragments (coalesced, once) ----
    uint32_t Br[4][4][2];   // [g][kt][2]
    {
        const uint32_t* bf = g_Bfrag + w * (4 * 4 * 64);
#pragma unroll
        for (int g = 0; g < 4; g++)
#pragma unroll
            for (int kt = 0; kt < 4; kt++) {
                uint2 v = *reinterpret_cast<const uint2*>(bf + (g * 4 + kt) * 64 + lane * 2);
                Br[g][kt][0] = v.x;
                Br[g][kt][1] = v.y;
            }
    }

    // ---- per-thread (u,b): gate g, hidden pair {j0,j1} ----
    float2 ub[8];
#pragma unroll
    for (int g = 0; g < 4; g++)
#pragma unroll
        for (int e = 0; e < 2; e++)
            ub[g * 2 + e] = g_ub[w * 32 + g * 8 + (lane & 3) * 2 + e];

    // ---- init c (f32 regs) and h (s8, t=0 scale 127/4 for unbounded hx0) ----
    const int r  = lane >> 2;
    const int j0 = w * 8 + (lane & 3) * 2;
    float c[4];   // {r:j0, r:j1, r+8:j0, r+8:j1}
    {
        c[0] = cx0[(rowbase + r) * Hsz + j0];
        c[1] = cx0[(rowbase + r) * Hsz + j0 + 1];
        c[2] = cx0[(rowbase + r + 8) * Hsz + j0];
        c[3] = cx0[(rowbase + r + 8) * Hsz + j0 + 1];
        float h00 = hx0[(rowbase + r) * Hsz + j0];
        float h01 = hx0[(rowbase + r) * Hsz + j0 + 1];
        float h10 = hx0[(rowbase + r + 8) * Hsz + j0];
        float h11 = hx0[(rowbase + r + 8) * Hsz + j0 + 1];
        uint32_t p0 = pack_s8(__float2int_rn(h01 * 31.75f), __float2int_rn(h00 * 31.75f));
        uint32_t p1 = pack_s8(__float2int_rn(h11 * 31.75f), __float2int_rn(h10 * 31.75f));
        *reinterpret_cast<uint16_t*>(dyn + OFF_H + r * HB + j0) = (uint16_t)p0;
        *reinterpret_cast<uint16_t*>(dyn + OFF_H + (r + 8) * HB + j0) = (uint16_t)p1;
    }
    if (tid < ROWS_PER_CTA) shX[0 * 16 + tid] = x[(rowbase + tid) * Tsz + 0];
    __syncthreads();

    // A-fragment base: row = lane>>2, k-byte = (lane&3)*4
    const uint32_t a_off = (uint32_t)((lane >> 2) * HB + (lane & 3) * 4);
    const __half2 h05 = __half2half2(__float2half(0.5f));

    for (int t = 0; t < Tsz; t++) {
        const int cur = t & 1, nxt = cur ^ 1;

        // gate scales (t=0: h stored with 4x coarser scale)
        const float scG = SWSH * ((t == 0) ? 4.0f : 1.0f);
        const float scI = 0.5f * scG;

        // ---- gx = x*u + b (independent of GEMM; overlaps) ----
        float xr0 = shX[cur * 16 + r];
        float xr8 = shX[cur * 16 + r + 8];
        float gx[4][4];
#pragma unroll
        for (int g = 0; g < 4; g++) {
            gx[g][0] = fmaf(xr0, ub[g * 2 + 0].x, ub[g * 2 + 0].y);
            gx[g][1] = fmaf(xr0, ub[g * 2 + 1].x, ub[g * 2 + 1].y);
            gx[g][2] = fmaf(xr8, ub[g * 2 + 0].x, ub[g * 2 + 0].y);
            gx[g][3] = fmaf(xr8, ub[g * 2 + 1].x, ub[g * 2 + 1].y);
        }

        float xnext = 0.0f;
        if (tid < ROWS_PER_CTA && (t + 1) < Tsz)
            xnext = x[(rowbase + tid) * Tsz + (t + 1)];

        // ---- GEMM: 4 k-tiles x 4 gates, s32 exact accumulation ----
        int acc[4][4];
#pragma unroll
        for (int g = 0; g < 4; g++)
            acc[g][0] = acc[g][1] = acc[g][2] = acc[g][3] = 0;

        const uint32_t abase = smem_base + OFF_H + (uint32_t)(cur * 16 * HB) + a_off;
#pragma unroll
        for (int kt = 0; kt < 4; kt++) {
            uint32_t ah[4];
            asm volatile("ld.shared.u32 %0, [%1];" : "=r"(ah[0]) : "r"(abase + kt * 32));
            asm volatile("ld.shared.u32 %0, [%1];" : "=r"(ah[1]) : "r"(abase + kt * 32 + 8 * HB));
            asm volatile("ld.shared.u32 %0, [%1];" : "=r"(ah[2]) : "r"(abase + kt * 32 + 16));
            asm volatile("ld.shared.u32 %0, [%1];" : "=r"(ah[3]) : "r"(abase + kt * 32 + 8 * HB + 16));
#pragma unroll
            for (int g = 0; g < 4; g++)
                mma_s8(acc[g], ah, Br[g][kt][0], Br[g][kt][1]);
        }

        // ---- epilogue: scale + full cell in registers, h2 SIMD ----
#pragma unroll
        for (int m = 0; m < 2; m++) {
            float gI0 = fmaf(acc2f(acc[0][2 * m]),     scI, gx[0][2 * m]);
            float gI1 = fmaf(acc2f(acc[0][2 * m + 1]), scI, gx[0][2 * m + 1]);
            float gF0 = fmaf(acc2f(acc[1][2 * m]),     scI, gx[1][2 * m]);
            float gF1 = fmaf(acc2f(acc[1][2 * m + 1]), scI, gx[1][2 * m + 1]);
            float gG0 = fmaf(acc2f(acc[2][2 * m]),     scG, gx[2][2 * m]);
            float gG1 = fmaf(acc2f(acc[2][2 * m + 1]), scG, gx[2][2 * m + 1]);
            float gO0 = fmaf(acc2f(acc[3][2 * m]),     scI, gx[3][2 * m]);
            float gO1 = fmaf(acc2f(acc[3][2 * m + 1]), scI, gx[3][2 * m + 1]);

            __half2 tI = tanh_h2(pack_h2(gI0, gI1));
            __half2 tF = tanh_h2(pack_h2(gF0, gF1));
            __half2 tG = tanh_h2(pack_h2(gG0, gG1));
            __half2 tO = tanh_h2(pack_h2(gO0, gO1));
            __half2 sI = __hfma2(tI, h05, h05);
            __half2 sF = __hfma2(tF, h05, h05);
            __half2 sO = __hfma2(tO, h05, h05);
            __half2 ig = __hmul2(sI, tG);
            float2 igf = __half22float2(ig);
            float2 vff = __half22float2(sF);
            c[2 * m + 0] = fmaf(vff.x, c[2 * m + 0], igf.x);
            c[2 * m + 1] = fmaf(vff.y, c[2 * m + 1], igf.y);
            __half2 tC = tanh_h2(pack_h2(c[2 * m + 0], c[2 * m + 1]));
            float2 sOf = __half22float2(sO);
            float2 tCf = __half22float2(tC);
            int q0 = __float2int_rn(sOf.x * tCf.x * 127.0f);
            int q1 = __float2int_rn(sOf.y * tCf.y * 127.0f);
            uint32_t pk = pack_s8(q1, q0);
            int row = (m == 0) ? r : (r + 8);
            *reinterpret_cast<uint16_t*>(dyn + OFF_H + nxt * 16 * HB + row * HB + j0) = (uint16_t)pk;
        }

        if (tid < ROWS_PER_CTA && (t + 1) < Tsz)
            shX[nxt * 16 + tid] = xnext;

        __syncthreads();
    }

    // ---- head: out[row] = sigmoid(sum_j h[row][j]*Wm[j] + bm) ----
    {
        const int j = tid & 127;
        const int q = tid >> 7;
        float wm = Wm[j] * (1.0f / 127.0f);
        float* sf = reinterpret_cast<float*>(dyn + OFF_SF);   // [16][128]
#pragma unroll
        for (int bq = 0; bq < 4; bq++) {
            int row = q * 4 + bq;
            float h = (float)(*reinterpret_cast<const int8_t*>(dyn + OFF_H + row * HB + j));
            sf[row * Hsz + j] = h * wm;
        }
        __syncthreads();

        if (tid < ROWS_PER_CTA) {
            float s = 0.0f;
#pragma unroll 8
            for (int k = 0; k < Hsz; k++) s += sf[tid * Hsz + k];
            s += bm[0];
            out[rowbase + tid] = fsig(s);
        }
    }
}

// ---------------------------------------------------------------------------
extern "C" void kernel_launch(void* const* d_in, const int* in_sizes, int n_in,
                              void* d_out, int out_size) {
    const float* x    = (const float*)d_in[0];
    const float* hx0  = (const float*)d_in[1];
    const float* cx0  = (const float*)d_in[2];
    const float* Wih  = (const float*)d_in[3];
    const float* Whh  = (const float*)d_in[4];
    const float* bih  = (const float*)d_in[5];
    const float* bhh  = (const float*)d_in[6];
    const float* Wmlp = (const float*)d_in[7];
    const float* bmlp = (const float*)d_in[8];
    float* out = (float*)d_out;

    cudaFuncSetAttribute(lstm_main_kernel,
                         cudaFuncAttributeMaxDynamicSharedMemorySize, DSMEM);

    lstm_prep_kernel<<<(16 * 4 * 4 * 64 + 255) / 256, 256>>>(Whh, Wih, bih, bhh);
    lstm_main_kernel<<<NCTA, NTHREADS, DSMEM>>>(x, hx0, cx0, Wmlp, bmlp, out);
}

// round 15
// speedup vs baseline: 2.3793x; 2.3793x over previous
#include <cuda_runtime.h>
#include <cuda_fp16.h>
#include <cstdint>

// LSTM_discriminator: B=2048, T=512, H=128, input dim 1.
// inputs: 0:x[2048,512] 1:hx0[2048,128] 2:cx0[2048,128] 3:W_ih[512,1]
//         4:W_hh[512,128] 5:b_ih[512] 6:b_hh[512] 7:W_mlp[1,128] 8:b_mlp[1]
// output: sigmoid(h_T @ W_mlp^T + b_mlp) -> [2048,1] fp32
//
// f16 tensor path (R11 structure), gate-major permutation: per step, per CTA
// (16 rows): gates^T[16,512] = h[16,128] @ W''^T with col = w*32 + g*8 + jl
// -> each thread's 4 acc sets are the full LSTM cell (i,f,g,o). No shuffles.
// This round: acc starts at 0 and gx = x*u + b is added in the epilogue, so
// the mma chain has no pre-dependency; t-loop unrolled 2x (static cur/nxt).

#define Bsz 2048
#define Tsz 512
#define Hsz 128
#define ROWS_PER_CTA 16
#define NCTA (Bsz / ROWS_PER_CTA)    // 128
#define NTHREADS 512
#define HROW 272                     // h row stride bytes (256 data + 16 pad)
#define KSTR 1040                    // staged W'' row stride bytes

#define OFF_H   0
#define OFF_X   8704
#define OFF_SF  8832
#define DSMEM   (128 * KSTR)         // 133120

__device__ __align__(16) __half g_Wperm16[128 * 512];  // [k][col] permuted + scaled W_hh fp16
__device__ float2 g_ub[512];                           // per permuted col: {scaled W_ih, scaled bias}

// ---------------------------------------------------------------------------
__device__ __forceinline__ uint32_t smem_u32(const void* p) {
    uint32_t a;
    asm("{ .reg .u64 t; cvta.to.shared.u64 t, %1; cvt.u32.u64 %0, t; }" : "=r"(a) : "l"(p));
    return a;
}
__device__ __forceinline__ void ldsm_x4(uint32_t* r, uint32_t addr) {
    asm volatile("ldmatrix.sync.aligned.m8n8.x4.shared.b16 {%0,%1,%2,%3}, [%4];"
        : "=r"(r[0]), "=r"(r[1]), "=r"(r[2]), "=r"(r[3]) : "r"(addr));
}
__device__ __forceinline__ void ldsm_x4_t(uint32_t* r, uint32_t addr) {
    asm volatile("ldmatrix.sync.aligned.m8n8.x4.trans.shared.b16 {%0,%1,%2,%3}, [%4];"
        : "=r"(r[0]), "=r"(r[1]), "=r"(r[2]), "=r"(r[3]) : "r"(addr));
}
__device__ __forceinline__ void mma16816(float* d, const uint32_t* a, uint32_t b0, uint32_t b1) {
    asm volatile(
        "mma.sync.aligned.m16n8k16.row.col.f32.f16.f16.f32 "
        "{%0,%1,%2,%3}, {%4,%5,%6,%7}, {%8,%9}, {%0,%1,%2,%3};"
        : "+f"(d[0]), "+f"(d[1]), "+f"(d[2]), "+f"(d[3])
        : "r"(a[0]), "r"(a[1]), "r"(a[2]), "r"(a[3]), "r"(b0), "r"(b1));
}
__device__ __forceinline__ uint32_t pack_h2(float lo, float hi) {
    uint32_t r; asm("cvt.rn.f16x2.f32 %0, %1, %2;" : "=r"(r) : "f"(hi), "f"(lo)); return r;
}
__device__ __forceinline__ __half2 tanh_h2(uint32_t x) {
    uint32_t r; asm("tanh.approx.f16x2 %0, %1;" : "=r"(r) : "r"(x));
    return *reinterpret_cast<__half2*>(&r);
}
__device__ __forceinline__ float tanha(float x) {
    float r; asm("tanh.approx.f32 %0, %1;" : "=f"(r) : "f"(x)); return r;
}
__device__ __forceinline__ float fsig(float x)  { return fmaf(0.5f, tanha(0.5f * x), 0.5f); }

// ---------------------------------------------------------------------------
// prep: permuted+scaled fp16 W'' [k][col], col = w*32 + g*8 + jl -> gate row
// g*128 + w*8 + jl ; rows for gates i,f,o scaled by 0.5 (sigma-halving folded).
// ---------------------------------------------------------------------------
__global__ void lstm_prep_kernel(const float* __restrict__ Whh,
                                 const float* __restrict__ Wih,
                                 const float* __restrict__ bih,
                                 const float* __restrict__ bhh) {
    int idx = blockIdx.x * blockDim.x + threadIdx.x;   // 0..65535
    if (idx >= 512 * 128) return;
    int col = idx >> 7;
    int k   = idx & 127;
    int w2  = col >> 5;
    int g   = (col >> 3) & 3;
    int jl  = col & 7;
    int grow = g * 128 + w2 * 8 + jl;
    float sc = (g == 2) ? 1.0f : 0.5f;
    g_Wperm16[k * 512 + col] = __float2half_rn(sc * Whh[grow * Hsz + k]);
    if (idx < 512) {
        int cw = idx >> 5, cg = (idx >> 3) & 3, cj = idx & 7;
        int gr2 = cg * 128 + cw * 8 + cj;
        float sc2 = (cg == 2) ? 1.0f : 0.5f;
        g_ub[idx] = make_float2(sc2 * Wih[gr2], sc2 * (bih[gr2] + bhh[gr2]));
    }
}

// ---------------------------------------------------------------------------
// main persistent kernel: 128 CTAs x 512 threads (16 warps).
// Warp w: B = W'' cols [w*32, w*32+32) register-resident (nt = gate type);
// thread: rows {r, r+8}, hidden pair j0 = w*8 + (lane&3)*2, j1 = j0+1.
// ---------------------------------------------------------------------------
__global__ __launch_bounds__(NTHREADS, 1)
void lstm_main_kernel(const float* __restrict__ x,
                      const float* __restrict__ hx0,
                      const float* __restrict__ cx0,
                      const float* __restrict__ Wm,
                      const float* __restrict__ bm,
                      float* __restrict__ out) {
    extern __shared__ __align__(16) char dyn[];
    const uint32_t smem_base = smem_u32(dyn);

    const int tid  = threadIdx.x;
    const int w    = tid >> 5;
    const int lane = tid & 31;
    const int rowbase = blockIdx.x * ROWS_PER_CTA;

    float* shX = reinterpret_cast<float*>(dyn + OFF_X);   // [2][16]

    // ---- stage permuted W'' into SMEM [128][KSTR] ----
    for (int i = tid; i < 128 * 64; i += NTHREADS) {
        int k = i >> 6, ch = i & 63;
        *reinterpret_cast<uint4*>(dyn + k * KSTR + ch * 16) =
            *reinterpret_cast<const uint4*>(g_Wperm16 + k * 512 + ch * 8);
    }
    __syncthreads();

    // ---- load B fragments ----
    const int sub = lane >> 3, r8v = lane & 7;
    uint32_t Br[4][8][2];   // [g][kt][2]
#pragma unroll
    for (int hhalf = 0; hhalf < 2; hhalf++) {
#pragma unroll
        for (int kt = 0; kt < 8; kt++) {
            uint32_t addr = smem_base
                + (uint32_t)((kt * 16 + r8v + (sub & 1) * 8) * KSTR)
                + (uint32_t)((w * 32 + hhalf * 16) * 2) + (uint32_t)((sub >> 1) * 16);
            uint32_t bb[4];
            ldsm_x4_t(bb, addr);
            Br[hhalf * 2 + 0][kt][0] = bb[0]; Br[hhalf * 2 + 0][kt][1] = bb[1];
            Br[hhalf * 2 + 1][kt][0] = bb[2]; Br[hhalf * 2 + 1][kt][1] = bb[3];
        }
    }
    __syncthreads();   // staging region now free -> persistent layout

    // ---- per-thread (u,b): gate g, hidden pair {j0,j1} -> ub[g*2+e] ----
    float2 ub[8];
#pragma unroll
    for (int g = 0; g < 4; g++)
#pragma unroll
        for (int e = 0; e < 2; e++)
            ub[g * 2 + e] = g_ub[w * 32 + g * 8 + (lane & 3) * 2 + e];

    // ---- init c (registers) and h (SMEM fp16 buf 0) ----
    const int r  = lane >> 2;
    const int j0 = w * 8 + (lane & 3) * 2;
    float c[4];   // {r:j0, r:j1, r+8:j0, r+8:j1}
    {
        c[0] = cx0[(rowbase + r) * Hsz + j0];
        c[1] = cx0[(rowbase + r) * Hsz + j0 + 1];
        c[2] = cx0[(rowbase + r + 8) * Hsz + j0];
        c[3] = cx0[(rowbase + r + 8) * Hsz + j0 + 1];
        float h00 = hx0[(rowbase + r) * Hsz + j0];
        float h01 = hx0[(rowbase + r) * Hsz + j0 + 1];
        float h10 = hx0[(rowbase + r + 8) * Hsz + j0];
        float h11 = hx0[(rowbase + r + 8) * Hsz + j0 + 1];
        *reinterpret_cast<uint32_t*>(dyn + OFF_H + r * HROW + j0 * 2) = pack_h2(h00, h01);
        *reinterpret_cast<uint32_t*>(dyn + OFF_H + (r + 8) * HROW + j0 * 2) = pack_h2(h10, h11);
    }
    if (tid < ROWS_PER_CTA) shX[0 * 16 + tid] = x[(rowbase + tid) * Tsz + 0];
    __syncthreads();

    const uint32_t a_lane_off = (uint32_t)((lane & 15) * HROW + (lane >> 4) * 16);
    const __half2 h05 = __half2half2(__float2half(0.5f));

#pragma unroll 2
    for (int t = 0; t < Tsz; t++) {
        const int cur = t & 1, nxt = cur ^ 1;

        // ---- GEMM first: acc from 0, no pre-dependency on gx ----
        float acc[4][4];
#pragma unroll
        for (int g = 0; g < 4; g++)
            acc[g][0] = acc[g][1] = acc[g][2] = acc[g][3] = 0.0f;

        const uint32_t abase = smem_base + OFF_H + (uint32_t)(cur * 16 * HROW) + a_lane_off;
#pragma unroll
        for (int kt = 0; kt < 8; kt++) {
            uint32_t ah[4];
            ldsm_x4(ah, abase + kt * 32);
#pragma unroll
            for (int g = 0; g < 4; g++)
                mma16816(acc[g], ah, Br[g][kt][0], Br[g][kt][1]);
        }

        // ---- gx = x*u + b: independent of mma; ptxas sinks into mma shadow ----
        float xr0 = shX[cur * 16 + r];
        float xr8 = shX[cur * 16 + r + 8];
        float gx[4][4];
#pragma unroll
        for (int g = 0; g < 4; g++) {
            gx[g][0] = fmaf(xr0, ub[g * 2 + 0].x, ub[g * 2 + 0].y);
            gx[g][1] = fmaf(xr0, ub[g * 2 + 1].x, ub[g * 2 + 1].y);
            gx[g][2] = fmaf(xr8, ub[g * 2 + 0].x, ub[g * 2 + 0].y);
            gx[g][3] = fmaf(xr8, ub[g * 2 + 1].x, ub[g * 2 + 1].y);
        }

        // x prefetch early
        float xnext = 0.0f;
        if (tid < ROWS_PER_CTA && (t + 1) < Tsz)
            xnext = x[(rowbase + tid) * Tsz + (t + 1)];

        // ---- epilogue: full cell in registers, h2 SIMD over the j-pair ----
#pragma unroll
        for (int m = 0; m < 2; m++) {
            // gates for (row r or r+8), j0/j1 pair; i,f,o pre-halved by prep
            __half2 tI = tanh_h2(pack_h2(acc[0][2 * m] + gx[0][2 * m], acc[0][2 * m + 1] + gx[0][2 * m + 1]));
            __half2 tF = tanh_h2(pack_h2(acc[1][2 * m] + gx[1][2 * m], acc[1][2 * m + 1] + gx[1][2 * m + 1]));
            __half2 tG = tanh_h2(pack_h2(acc[2][2 * m] + gx[2][2 * m], acc[2][2 * m + 1] + gx[2][2 * m + 1]));
            __half2 tO = tanh_h2(pack_h2(acc[3][2 * m] + gx[3][2 * m], acc[3][2 * m + 1] + gx[3][2 * m + 1]));
            __half2 sI = __hfma2(tI, h05, h05);
            __half2 sF = __hfma2(tF, h05, h05);
            __half2 sO = __hfma2(tO, h05, h05);
            __half2 ig = __hmul2(sI, tG);
            float2 igf = __half22float2(ig);
            float2 vff = __half22float2(sF);
            c[2 * m + 0] = fmaf(vff.x, c[2 * m + 0], igf.x);
            c[2 * m + 1] = fmaf(vff.y, c[2 * m + 1], igf.y);
            __half2 tC = tanh_h2(pack_h2(c[2 * m + 0], c[2 * m + 1]));
            __half2 h2v = __hmul2(sO, tC);
            int row = (m == 0) ? r : (r + 8);
            *reinterpret_cast<__half2*>(dyn + OFF_H + nxt * 16 * HROW + row * HROW + j0 * 2) = h2v;
        }

        if (tid < ROWS_PER_CTA && (t + 1) < Tsz)
            shX[nxt * 16 + tid] = xnext;

        __syncthreads();
    }

    // ---- head: out[row] = sigmoid(sum_j h[row][j]*Wm[j] + bm) ----
    {
        const int j = tid & 127;
        const int q = tid >> 7;
        float wm = Wm[j];
        float* sf = reinterpret_cast<float*>(dyn + OFF_SF);   // [16][128]
#pragma unroll
        for (int bq = 0; bq < 4; bq++) {
            int row = q * 4 + bq;
            float h = __half2float(
                *reinterpret_cast<const __half*>(dyn + OFF_H + 0 * 16 * HROW + row * HROW + j * 2));
            sf[row * Hsz + j] = h * wm;
        }
        __syncthreads();

        if (tid < ROWS_PER_CTA) {
            float s = 0.0f;
#pragma unroll 8
            for (int k = 0; k < Hsz; k++) s += sf[tid * Hsz + k];
            s += bm[0];
            out[rowbase + tid] = fsig(s);
        }
    }
}

// ---------------------------------------------------------------------------
extern "C" void kernel_launch(void* const* d_in, const int* in_sizes, int n_in,
                              void* d_out, int out_size) {
    const float* x    = (const float*)d_in[0];
    const float* hx0  = (const float*)d_in[1];
    const float* cx0  = (const float*)d_in[2];
    const float* Wih  = (const float*)d_in[3];
    const float* Whh  = (const float*)d_in[4];
    const float* bih  = (const float*)d_in[5];
    const float* bhh  = (const float*)d_in[6];
    const float* Wmlp = (const float*)d_in[7];
    const float* bmlp = (const float*)d_in[8];
    float* out = (float*)d_out;

    cudaFuncSetAttribute(lstm_main_kernel,
                         cudaFuncAttributeMaxDynamicSharedMemorySize, DSMEM);

    lstm_prep_kernel<<<(512 * 128 + 255) / 256, 256>>>(Whh, Wih, bih, bhh);
    lstm_main_kernel<<<NCTA, NTHREADS, DSMEM>>>(x, hx0, cx0, Wmlp, bmlp, out);
}